// round 10
// baseline (speedup 1.0000x reference)
#include <cuda_runtime.h>
#include <math.h>
#include <stdint.h>

#define BB 4
#define SQ 2048
#define EE 1024
#define HH 16
#define DH 64

#define GM (BB*SQ)     // 8192
#define GN (3*EE)      // 3072
#define GK (EE)        // 1024

// GEMM tiling
#define TM 128
#define TN 128
#define TKS 32
#define PAD 36
#define ABUF (TM*PAD)

// Scratch: q,k [B,H,S,Dh]; v transposed [B,H,Dh,S]  (all tf32-pre-rounded)
__device__ float g_q[(size_t)BB * HH * SQ * DH];
__device__ float g_k[(size_t)BB * HH * SQ * DH];
__device__ float g_v[(size_t)BB * HH * DH * SQ];

__device__ __forceinline__ uint32_t f2tf32(float x) {
    uint32_t r;
    asm("cvt.rna.tf32.f32 %0, %1;" : "=r"(r) : "f"(x));
    return r;
}
__device__ __forceinline__ float tf32r(float x) { return __uint_as_float(f2tf32(x)); }

#define MMA_TF32(acc, a0, a1, a2, a3, b0, b1)                                \
    asm volatile(                                                            \
        "mma.sync.aligned.m16n8k8.row.col.f32.tf32.tf32.f32 "                \
        "{%0,%1,%2,%3}, {%4,%5,%6,%7}, {%8,%9}, {%0,%1,%2,%3};\n"            \
        : "+f"(acc[0]), "+f"(acc[1]), "+f"(acc[2]), "+f"(acc[3])             \
        : "r"(a0), "r"(a1), "r"(a2), "r"(a3), "r"(b0), "r"(b1))

// ---------------------------------------------------------------------------
// QKV GEMM (TF32): qkv = x @ W^T, scatter into g_k/g_q/g_v (tf32-rounded).
// (unchanged from validated round-9 version)
// ---------------------------------------------------------------------------
__global__ __launch_bounds__(256, 2) void qkv_gemm_tf32(
    const float* __restrict__ A, const float* __restrict__ W,
    float* __restrict__ gq, float* __restrict__ gk, float* __restrict__ gv)
{
    extern __shared__ float gs[];
    float* As = gs;
    float* Bs = gs + 2 * ABUF;

    const int tid  = threadIdx.x;
    const int lane = tid & 31;
    const int wid  = tid >> 5;
    const int wm   = wid & 3;
    const int wn   = wid >> 2;
    const int g    = lane >> 2;
    const int tig  = lane & 3;
    const int m0   = blockIdx.y * TM;
    const int n0   = blockIdx.x * TN;

    const uint32_t s_base = (uint32_t)__cvta_generic_to_shared(gs);

    float acc[2][8][4] = {};

    auto issue = [&](int s, int buf) {
        const int k0 = s * TKS;
        #pragma unroll
        for (int i = 0; i < 4; i++) {
            int c   = tid + i * 256;
            int row = c >> 3;
            int kc  = (c & 7) * 4;
            const float* srcA = A + (size_t)(m0 + row) * GK + k0 + kc;
            uint32_t dstA = s_base + (uint32_t)(buf * ABUF + row * PAD + kc) * 4u;
            asm volatile("cp.async.cg.shared.global [%0], [%1], 16;\n" :: "r"(dstA), "l"(srcA));
            const float* srcB = W + (size_t)(n0 + row) * GK + k0 + kc;
            uint32_t dstB = s_base + (uint32_t)(2 * ABUF * 4u) + (uint32_t)(buf * ABUF + row * PAD + kc) * 4u;
            asm volatile("cp.async.cg.shared.global [%0], [%1], 16;\n" :: "r"(dstB), "l"(srcB));
        }
        asm volatile("cp.async.commit_group;\n" ::);
    };

    const int NS = GK / TKS;
    issue(0, 0);

    for (int s = 0; s < NS; s++) {
        const int cur = s & 1;
        if (s + 1 < NS) {
            issue(s + 1, cur ^ 1);
            asm volatile("cp.async.wait_group 1;\n" ::);
        } else {
            asm volatile("cp.async.wait_group 0;\n" ::);
        }
        __syncthreads();

        const float* Ab = As + cur * ABUF + (wm * 32) * PAD;
        const float* Bb = Bs + cur * ABUF + (wn * 64) * PAD;

        #pragma unroll
        for (int kk = 0; kk < TKS; kk += 8) {
            uint32_t bf[8][2];
            #pragma unroll
            for (int nt = 0; nt < 8; nt++) {
                bf[nt][0] = f2tf32(Bb[(nt * 8 + g) * PAD + kk + tig]);
                bf[nt][1] = f2tf32(Bb[(nt * 8 + g) * PAD + kk + tig + 4]);
            }
            #pragma unroll
            for (int mt = 0; mt < 2; mt++) {
                uint32_t af[4];
                af[0] = f2tf32(Ab[(mt * 16 + g) * PAD     + kk + tig]);
                af[1] = f2tf32(Ab[(mt * 16 + g + 8) * PAD + kk + tig]);
                af[2] = f2tf32(Ab[(mt * 16 + g) * PAD     + kk + tig + 4]);
                af[3] = f2tf32(Ab[(mt * 16 + g + 8) * PAD + kk + tig + 4]);
                #pragma unroll
                for (int nt = 0; nt < 8; nt++)
                    MMA_TF32(acc[mt][nt], af[0], af[1], af[2], af[3], bf[nt][0], bf[nt][1]);
            }
        }
        __syncthreads();
    }

    #pragma unroll
    for (int mt = 0; mt < 2; mt++) {
        #pragma unroll
        for (int nt = 0; nt < 8; nt++) {
            const int cc    = n0 + wn * 64 + nt * 8 + 2 * tig;
            const int chunk = cc >> 10;
            const int hd    = (cc & 1023) >> 6;
            const int d     = cc & 63;
            #pragma unroll
            for (int half = 0; half < 2; half++) {
                const int r = m0 + wm * 32 + mt * 16 + g + half * 8;
                const int b = r >> 11, srow = r & 2047;
                const float c0 = tf32r(acc[mt][nt][half * 2 + 0]);
                const float c1 = tf32r(acc[mt][nt][half * 2 + 1]);
                const size_t bh = (size_t)(b * HH + hd);
                if (chunk == 0) {
                    *(float2*)&gk[(bh * SQ + srow) * DH + d] = make_float2(c0, c1);
                } else if (chunk == 1) {
                    *(float2*)&gq[(bh * SQ + srow) * DH + d] = make_float2(c0, c1);
                } else {
                    gv[(bh * DH + d) * SQ + srow]     = c0;
                    gv[(bh * DH + d + 1) * SQ + srow] = c1;
                }
            }
        }
    }
}

// ---------------------------------------------------------------------------
// Flash-style causal ALiBi attention, TF32 MMA, 2 passes.
// CTA = (b, h, 16 query rows), 256 threads = 8 warps.
// Q fragments preloaded to registers (no smem). PV split by key-slab:
// warp w owns keys w*8..w*8+7 across ALL 64 dims; one end-of-CTA reduction.
// ---------------------------------------------------------------------------
__global__ __launch_bounds__(256, 2) void attn_flash(
    const float* __restrict__ gq, const float* __restrict__ gk,
    const float* __restrict__ gv, float* __restrict__ out,
    float* __restrict__ attn, int write_attn)
{
    __shared__ float pool[8704];           // kt[64*68] + vt[64*68]; reused as redf[8*16*64]
    __shared__ float pt[16 * 68];
    __shared__ float red1[8][16][2];
    __shared__ float rowstats[16][2];

    float* kt = pool;
    float* vt = pool + 4352;

    const int i0 = (gridDim.x - 1 - blockIdx.x) * 16;   // longest tiles first
    const int h  = blockIdx.y;
    const int b  = blockIdx.z;
    const int tid  = threadIdx.x;
    const int lane = tid & 31;
    const int w    = tid >> 5;            // warp 0..7
    const int g    = lane >> 2;           // 0..7
    const int tig  = lane & 3;            // 0..3

    const size_t bh   = (size_t)(b * HH + h);
    const float slope = exp2f(-0.5f * (float)(h + 1));
    const float inv_scale = 1.0f / 32.0f;

    const int jend = (((i0 + 15) >> 6) + 1) << 6;
    const int gi0 = i0 + g, gi1 = i0 + g + 8;

    // --- preload Q fragments straight from gmem (tf32-pre-rounded) ---
    uint32_t qa[8][4];
    {
        const float* q0 = gq + (bh * SQ + i0 + g) * DH;
        const float* q1 = gq + (bh * SQ + i0 + g + 8) * DH;
        #pragma unroll
        for (int kk = 0; kk < 8; kk++) {
            qa[kk][0] = __float_as_uint(q0[kk * 8 + tig]);
            qa[kk][1] = __float_as_uint(q1[kk * 8 + tig]);
            qa[kk][2] = __float_as_uint(q0[kk * 8 + tig + 4]);
            qa[kk][3] = __float_as_uint(q1[kk * 8 + tig + 4]);
        }
    }

    // =================== pass 1: online (max, sum) ===================
    float m0 = -INFINITY, m1 = -INFINITY, s0 = 0.f, s1 = 0.f;

    for (int jt = 0; jt < jend; jt += 64) {
        for (int idx = tid; idx < 64 * 16; idx += 256) {
            int key = idx >> 4, dc = (idx & 15) * 4;
            *(float4*)&kt[key * 68 + dc] = *(const float4*)&gk[(bh * SQ + jt + key) * DH + dc];
        }
        __syncthreads();

        float acc[4] = {};
        #pragma unroll
        for (int kk = 0; kk < 8; kk++) {
            uint32_t b0 = __float_as_uint(kt[(w * 8 + g) * 68 + kk * 8 + tig]);
            uint32_t b1 = __float_as_uint(kt[(w * 8 + g) * 68 + kk * 8 + tig + 4]);
            MMA_TF32(acc, qa[kk][0], qa[kk][1], qa[kk][2], qa[kk][3], b0, b1);
        }
        __syncthreads();

        const int j0 = jt + w * 8 + 2 * tig;
        float v00 = (j0     <= gi0) ? fmaf(slope, (float)(j0 - gi0),     acc[0] * inv_scale) : -INFINITY;
        float v01 = (j0 + 1 <= gi0) ? fmaf(slope, (float)(j0 + 1 - gi0), acc[1] * inv_scale) : -INFINITY;
        float v10 = (j0     <= gi1) ? fmaf(slope, (float)(j0 - gi1),     acc[2] * inv_scale) : -INFINITY;
        float v11 = (j0 + 1 <= gi1) ? fmaf(slope, (float)(j0 + 1 - gi1), acc[3] * inv_scale) : -INFINITY;

        float nm0 = fmaxf(m0, fmaxf(v00, v01));
        if (nm0 > -INFINITY) {
            s0 = s0 * __expf(m0 - nm0) + __expf(v00 - nm0) + __expf(v01 - nm0);
            m0 = nm0;
        }
        float nm1 = fmaxf(m1, fmaxf(v10, v11));
        if (nm1 > -INFINITY) {
            s1 = s1 * __expf(m1 - nm1) + __expf(v10 - nm1) + __expf(v11 - nm1);
            m1 = nm1;
        }
    }

    // quad reduce (across tig), then cross-warp
    #pragma unroll
    for (int o = 1; o <= 2; o <<= 1) {
        float om = __shfl_xor_sync(0xffffffffu, m0, o);
        float os = __shfl_xor_sync(0xffffffffu, s0, o);
        float nm = fmaxf(m0, om);
        s0 = (nm > -INFINITY) ? s0 * __expf(m0 - nm) + os * __expf(om - nm) : 0.f;
        m0 = nm;
        om = __shfl_xor_sync(0xffffffffu, m1, o);
        os = __shfl_xor_sync(0xffffffffu, s1, o);
        nm = fmaxf(m1, om);
        s1 = (nm > -INFINITY) ? s1 * __expf(m1 - nm) + os * __expf(om - nm) : 0.f;
        m1 = nm;
    }
    if (tig == 0) {
        red1[w][g][0] = m0;     red1[w][g][1] = s0;
        red1[w][g + 8][0] = m1; red1[w][g + 8][1] = s1;
    }
    __syncthreads();
    if (tid < 16) {
        float m = -INFINITY, s = 0.f;
        #pragma unroll
        for (int p = 0; p < 8; p++) {
            float pm = red1[p][tid][0], ps = red1[p][tid][1];
            float nm = fmaxf(m, pm);
            s = (nm > -INFINITY) ? s * __expf(m - nm) + ps * __expf(pm - nm) : 0.f;
            m = nm;
        }
        rowstats[tid][0] = m;
        rowstats[tid][1] = 1.0f / s;
    }
    __syncthreads();
    const float rm0 = rowstats[g][0],     ri0 = rowstats[g][1];
    const float rm1 = rowstats[g + 8][0], ri1 = rowstats[g + 8][1];

    // =================== pass 2: probs + PV (key-slab split) ===================
    float pacc[8][4] = {};   // warp w: keys w*8.., all 64 dims (nt)

    for (int jt = 0; jt < jend; jt += 64) {
        for (int idx = tid; idx < 64 * 16; idx += 256) {
            int key = idx >> 4, dc = (idx & 15) * 4;
            *(float4*)&kt[key * 68 + dc] = *(const float4*)&gk[(bh * SQ + jt + key) * DH + dc];
        }
        for (int idx = tid; idx < 64 * 16; idx += 256) {
            int d = idx >> 4, jc = (idx & 15) * 4;
            *(float4*)&vt[d * 68 + jc] = *(const float4*)&gv[(bh * DH + d) * SQ + jt + jc];
        }
        __syncthreads();

        float acc[4] = {};
        #pragma unroll
        for (int kk = 0; kk < 8; kk++) {
            uint32_t b0 = __float_as_uint(kt[(w * 8 + g) * 68 + kk * 8 + tig]);
            uint32_t b1 = __float_as_uint(kt[(w * 8 + g) * 68 + kk * 8 + tig + 4]);
            MMA_TF32(acc, qa[kk][0], qa[kk][1], qa[kk][2], qa[kk][3], b0, b1);
        }

        const int j0 = jt + w * 8 + 2 * tig;
        float v00 = (j0     <= gi0) ? fmaf(slope, (float)(j0 - gi0),     acc[0] * inv_scale) : -INFINITY;
        float v01 = (j0 + 1 <= gi0) ? fmaf(slope, (float)(j0 + 1 - gi0), acc[1] * inv_scale) : -INFINITY;
        float v10 = (j0     <= gi1) ? fmaf(slope, (float)(j0 - gi1),     acc[2] * inv_scale) : -INFINITY;
        float v11 = (j0 + 1 <= gi1) ? fmaf(slope, (float)(j0 + 1 - gi1), acc[3] * inv_scale) : -INFINITY;

        float p00 = __expf(v00 - rm0) * ri0;
        float p01 = __expf(v01 - rm0) * ri0;
        float p10 = __expf(v10 - rm1) * ri1;
        float p11 = __expf(v11 - rm1) * ri1;

        if (write_attn) {
            *(float2*)&attn[(bh * SQ + i0 + g) * SQ + j0]     = make_float2(p00, p01);
            *(float2*)&attn[(bh * SQ + i0 + g + 8) * SQ + j0] = make_float2(p10, p11);
        }

        const int pc = w * 8 + 2 * tig;
        *(float2*)&pt[g * 68 + pc]       = make_float2(tf32r(p00), tf32r(p01));
        *(float2*)&pt[(g + 8) * 68 + pc] = make_float2(tf32r(p10), tf32r(p11));
        __syncthreads();

        // PV: warp w's key slab (k = w*8..w*8+7), all dims; A-frag loaded ONCE
        {
            uint32_t a0 = __float_as_uint(pt[g * 68       + w * 8 + tig]);
            uint32_t a1 = __float_as_uint(pt[(g + 8) * 68 + w * 8 + tig]);
            uint32_t a2 = __float_as_uint(pt[g * 68       + w * 8 + tig + 4]);
            uint32_t a3 = __float_as_uint(pt[(g + 8) * 68 + w * 8 + tig + 4]);
            #pragma unroll
            for (int nt = 0; nt < 8; nt++) {
                uint32_t b0 = __float_as_uint(vt[(nt * 8 + g) * 68 + w * 8 + tig]);
                uint32_t b1 = __float_as_uint(vt[(nt * 8 + g) * 68 + w * 8 + tig + 4]);
                MMA_TF32(pacc[nt], a0, a1, a2, a3, b0, b1);
            }
        }
        __syncthreads();
    }

    // --- final cross-warp reduction over key slabs (overlay on kt/vt) ---
    float* redf = pool;    // 8 * 16 * 64 = 8192 floats
    #pragma unroll
    for (int nt = 0; nt < 8; nt++) {
        const int col = nt * 8 + 2 * tig;
        *(float2*)&redf[w * 1024 + g * 64 + col]       = make_float2(pacc[nt][0], pacc[nt][1]);
        *(float2*)&redf[w * 1024 + (g + 8) * 64 + col] = make_float2(pacc[nt][2], pacc[nt][3]);
    }
    __syncthreads();
    {
        const int row = tid >> 4, dc = (tid & 15) * 4;
        float4 s = *(const float4*)&redf[row * 64 + dc];
        #pragma unroll
        for (int p = 1; p < 8; p++) {
            float4 t = *(const float4*)&redf[p * 1024 + row * 64 + dc];
            s.x += t.x; s.y += t.y; s.z += t.z; s.w += t.w;
        }
        *(float4*)&out[(size_t)(b * SQ + i0 + row) * EE + h * DH + dc] = s;
    }

    // tail zero-fill of attn rows beyond causal extent
    if (write_attn) {
        const float4 z = make_float4(0.f, 0.f, 0.f, 0.f);
        for (int r = 0; r < 16; r++) {
            float* arow = attn + (bh * SQ + i0 + r) * SQ;
            for (int j = jend + tid * 4; j < SQ; j += 1024)
                *(float4*)&arow[j] = z;
        }
    }
}

// ---------------------------------------------------------------------------
extern "C" void kernel_launch(void* const* d_in, const int* in_sizes, int n_in,
                              void* d_out, int out_size)
{
    const float* x = (const float*)d_in[0];
    const float* W = (const float*)d_in[1];
    float* out = (float*)d_out;

    const long out_elems  = (long)BB * SQ * EE;
    const long attn_elems = (long)BB * HH * SQ * SQ;
    int write_attn = ((long)out_size >= out_elems + attn_elems) ? 1 : 0;
    float* attn = write_attn ? (out + out_elems) : nullptr;

    float *gq, *gk, *gv;
    cudaGetSymbolAddress((void**)&gq, g_q);
    cudaGetSymbolAddress((void**)&gk, g_k);
    cudaGetSymbolAddress((void**)&gv, g_v);

    // QKV projection (TF32 tensor cores) + tf32-rounded scatter
    {
        int gemm_smem = 4 * ABUF * (int)sizeof(float);
        cudaFuncSetAttribute(qkv_gemm_tf32, cudaFuncAttributeMaxDynamicSharedMemorySize, gemm_smem);
        dim3 grid(GN / TN, GM / TM);
        qkv_gemm_tf32<<<grid, 256, gemm_smem>>>(x, W, gq, gk, gv);
    }

    // Flash attention (TF32 MMA, 2-pass, key-slab PV)
    {
        dim3 grid(SQ / 16, HH, BB);
        attn_flash<<<grid, 256>>>(gq, gk, gv, out, attn, write_attn);
    }
}

// round 11
// speedup vs baseline: 1.5341x; 1.5341x over previous
#include <cuda_runtime.h>
#include <math.h>
#include <stdint.h>

#define BB 4
#define SQ 2048
#define EE 1024
#define HH 16
#define DH 64
#define ROWS 16
#define KT 256

#define GM (BB*SQ)     // 8192
#define GN (3*EE)      // 3072
#define GK (EE)        // 1024

// GEMM tiling
#define TM 128
#define TN 128
#define TKS 32
#define PAD 36
#define ABUF (TM*PAD)

#define SCP 2052       // sc row pitch (mod 32 banks = 4)

// Scratch: q,k [B,H,S,Dh]; v transposed [B,H,Dh,S]  (tf32-pre-rounded)
__device__ float g_q[(size_t)BB * HH * SQ * DH];
__device__ float g_k[(size_t)BB * HH * SQ * DH];
__device__ float g_v[(size_t)BB * HH * DH * SQ];

__device__ __forceinline__ uint32_t f2tf32(float x) {
    uint32_t r;
    asm("cvt.rna.tf32.f32 %0, %1;" : "=r"(r) : "f"(x));
    return r;
}
__device__ __forceinline__ float tf32r(float x) { return __uint_as_float(f2tf32(x)); }

#define MMA_TF32(acc, a0, a1, a2, a3, b0, b1)                                \
    asm volatile(                                                            \
        "mma.sync.aligned.m16n8k8.row.col.f32.tf32.tf32.f32 "                \
        "{%0,%1,%2,%3}, {%4,%5,%6,%7}, {%8,%9}, {%0,%1,%2,%3};\n"            \
        : "+f"(acc[0]), "+f"(acc[1]), "+f"(acc[2]), "+f"(acc[3])             \
        : "r"(a0), "r"(a1), "r"(a2), "r"(a3), "r"(b0), "r"(b1))

// ---------------------------------------------------------------------------
// QKV GEMM (TF32): qkv = x @ W^T, scatter into g_k/g_q/g_v (tf32-rounded).
// ---------------------------------------------------------------------------
__global__ __launch_bounds__(256, 2) void qkv_gemm_tf32(
    const float* __restrict__ A, const float* __restrict__ W,
    float* __restrict__ gq, float* __restrict__ gk, float* __restrict__ gv)
{
    extern __shared__ float gs[];
    float* As = gs;
    float* Bs = gs + 2 * ABUF;

    const int tid  = threadIdx.x;
    const int lane = tid & 31;
    const int wid  = tid >> 5;
    const int wm   = wid & 3;
    const int wn   = wid >> 2;
    const int g    = lane >> 2;
    const int tig  = lane & 3;
    const int m0   = blockIdx.y * TM;
    const int n0   = blockIdx.x * TN;

    const uint32_t s_base = (uint32_t)__cvta_generic_to_shared(gs);

    float acc[2][8][4] = {};

    auto issue = [&](int s, int buf) {
        const int k0 = s * TKS;
        #pragma unroll
        for (int i = 0; i < 4; i++) {
            int c   = tid + i * 256;
            int row = c >> 3;
            int kc  = (c & 7) * 4;
            const float* srcA = A + (size_t)(m0 + row) * GK + k0 + kc;
            uint32_t dstA = s_base + (uint32_t)(buf * ABUF + row * PAD + kc) * 4u;
            asm volatile("cp.async.cg.shared.global [%0], [%1], 16;\n" :: "r"(dstA), "l"(srcA));
            const float* srcB = W + (size_t)(n0 + row) * GK + k0 + kc;
            uint32_t dstB = s_base + (uint32_t)(2 * ABUF * 4u) + (uint32_t)(buf * ABUF + row * PAD + kc) * 4u;
            asm volatile("cp.async.cg.shared.global [%0], [%1], 16;\n" :: "r"(dstB), "l"(srcB));
        }
        asm volatile("cp.async.commit_group;\n" ::);
    };

    const int NS = GK / TKS;
    issue(0, 0);

    for (int s = 0; s < NS; s++) {
        const int cur = s & 1;
        if (s + 1 < NS) {
            issue(s + 1, cur ^ 1);
            asm volatile("cp.async.wait_group 1;\n" ::);
        } else {
            asm volatile("cp.async.wait_group 0;\n" ::);
        }
        __syncthreads();

        const float* Ab = As + cur * ABUF + (wm * 32) * PAD;
        const float* Bb = Bs + cur * ABUF + (wn * 64) * PAD;

        #pragma unroll
        for (int kk = 0; kk < TKS; kk += 8) {
            uint32_t bf[8][2];
            #pragma unroll
            for (int nt = 0; nt < 8; nt++) {
                bf[nt][0] = f2tf32(Bb[(nt * 8 + g) * PAD + kk + tig]);
                bf[nt][1] = f2tf32(Bb[(nt * 8 + g) * PAD + kk + tig + 4]);
            }
            #pragma unroll
            for (int mt = 0; mt < 2; mt++) {
                uint32_t af[4];
                af[0] = f2tf32(Ab[(mt * 16 + g) * PAD     + kk + tig]);
                af[1] = f2tf32(Ab[(mt * 16 + g + 8) * PAD + kk + tig]);
                af[2] = f2tf32(Ab[(mt * 16 + g) * PAD     + kk + tig + 4]);
                af[3] = f2tf32(Ab[(mt * 16 + g + 8) * PAD + kk + tig + 4]);
                #pragma unroll
                for (int nt = 0; nt < 8; nt++)
                    MMA_TF32(acc[mt][nt], af[0], af[1], af[2], af[3], bf[nt][0], bf[nt][1]);
            }
        }
        __syncthreads();
    }

    // epilogue: tf32-round, scatter to g_k (chunk 0), g_q (chunk 1), g_v^T (chunk 2)
    #pragma unroll
    for (int mt = 0; mt < 2; mt++) {
        #pragma unroll
        for (int nt = 0; nt < 8; nt++) {
            const int cc    = n0 + wn * 64 + nt * 8 + 2 * tig;
            const int chunk = cc >> 10;
            const int hd    = (cc & 1023) >> 6;
            const int d     = cc & 63;
            #pragma unroll
            for (int half = 0; half < 2; half++) {
                const int r = m0 + wm * 32 + mt * 16 + g + half * 8;
                const int b = r >> 11, srow = r & 2047;
                const float c0 = tf32r(acc[mt][nt][half * 2 + 0]);
                const float c1 = tf32r(acc[mt][nt][half * 2 + 1]);
                const size_t bh = (size_t)(b * HH + hd);
                if (chunk == 0) {
                    *(float2*)&gk[(bh * SQ + srow) * DH + d] = make_float2(c0, c1);
                } else if (chunk == 1) {
                    *(float2*)&gq[(bh * SQ + srow) * DH + d] = make_float2(c0, c1);
                } else {
                    gv[(bh * DH + d) * SQ + srow]     = c0;
                    gv[(bh * DH + d + 1) * SQ + srow] = c1;
                }
            }
        }
    }
}

// ---------------------------------------------------------------------------
// Fused causal ALiBi attention with TF32 MMA scores + PV (R8 structure,
// raw fragment loads from pre-rounded operands — cvt removed).
// One CTA per (b, h, 16-row query tile). 512 threads = 16 warps.
// ---------------------------------------------------------------------------
__global__ __launch_bounds__(512, 1) void attn_kernel(
    const float* __restrict__ gq, const float* __restrict__ gk,
    const float* __restrict__ gv, float* __restrict__ out,
    float* __restrict__ attn, int write_attn)
{
    extern __shared__ float smem[];
    float* sc   = smem;                    // 16 * SCP
    float* kq   = sc + ROWS * SCP;         // 17408 floats
    float* qs   = kq + 17408;              // 16 * 68
    float* sinv = qs + ROWS * 68;          // 16

    const int i0 = (gridDim.x - 1 - blockIdx.x) * ROWS;   // longest tiles first
    const int h  = blockIdx.y;
    const int b  = blockIdx.z;
    const int tid  = threadIdx.x;
    const int lane = tid & 31;
    const int w    = tid >> 5;             // warp 0..15
    const int g    = lane >> 2;            // 0..7
    const int tig  = lane & 3;             // 0..3

    const size_t bh   = (size_t)(b * HH + h);
    const float slope = exp2f(-0.5f * (float)(h + 1));
    const float inv_scale = 1.0f / 32.0f;

    // --- load Q (16 x 64), pre-rounded tf32 ---
    if (tid < 256) {
        int r = tid >> 4, dc = (tid & 15) * 4;
        float4 v = *(const float4*)&gq[(bh * SQ + i0 + r) * DH + dc];
        *(float4*)&qs[r * 68 + dc] = v;
    }
    __syncthreads();

    const int jend = ((i0 + ROWS - 1) / 64 + 1) * 64;

    // --- preload Q fragments (rows g, g+8), raw bits ---
    uint32_t qa[8][4];
    #pragma unroll
    for (int kk = 0; kk < 8; kk++) {
        qa[kk][0] = __float_as_uint(qs[g * 68       + kk * 8 + tig]);
        qa[kk][1] = __float_as_uint(qs[(g + 8) * 68 + kk * 8 + tig]);
        qa[kk][2] = __float_as_uint(qs[g * 68       + kk * 8 + tig + 4]);
        qa[kk][3] = __float_as_uint(qs[(g + 8) * 68 + kk * 8 + tig + 4]);
    }

    // ======================= scores (MMA) =======================
    for (int jt = 0; jt < jend; jt += KT) {
        const int ktile = min(KT, jend - jt);
        for (int idx = tid; idx < ktile * 16; idx += 512) {
            int key = idx >> 4, dc = (idx & 15) * 4;
            float4 v = *(const float4*)&gk[(bh * SQ + jt + key) * DH + dc];
            *(float4*)&kq[key * 68 + dc] = v;
        }
        __syncthreads();

        const int kb = w * 16;
        if (kb < ktile) {
            float acc[2][4] = {};
            #pragma unroll
            for (int kk = 0; kk < 8; kk++) {
                #pragma unroll
                for (int nt = 0; nt < 2; nt++) {
                    uint32_t b0 = __float_as_uint(kq[(kb + nt * 8 + g) * 68 + kk * 8 + tig]);
                    uint32_t b1 = __float_as_uint(kq[(kb + nt * 8 + g) * 68 + kk * 8 + tig + 4]);
                    MMA_TF32(acc[nt], qa[kk][0], qa[kk][1], qa[kk][2], qa[kk][3], b0, b1);
                }
            }
            #pragma unroll
            for (int nt = 0; nt < 2; nt++) {
                const int j0 = jt + kb + nt * 8 + 2 * tig;
                #pragma unroll
                for (int half = 0; half < 2; half++) {
                    const int row = g + half * 8;
                    const int gi  = i0 + row;
                    float v0 = (j0     <= gi) ? fmaf(slope, (float)(j0 - gi),     acc[nt][half*2+0] * inv_scale) : -INFINITY;
                    float v1 = (j0 + 1 <= gi) ? fmaf(slope, (float)(j0 + 1 - gi), acc[nt][half*2+1] * inv_scale) : -INFINITY;
                    *(float2*)&sc[row * SCP + j0] = make_float2(v0, v1);
                }
            }
        }
        __syncthreads();
    }

    // ======================= softmax (warp w owns row w) =======================
    {
        float* row = sc + w * SCP;
        float mx = -INFINITY;
        for (int j = lane * 4; j < jend; j += 128) {
            float4 v = *(const float4*)(row + j);
            mx = fmaxf(mx, fmaxf(fmaxf(v.x, v.y), fmaxf(v.z, v.w)));
        }
        #pragma unroll
        for (int o = 16; o; o >>= 1) mx = fmaxf(mx, __shfl_xor_sync(0xffffffffu, mx, o));
        float sum = 0.f;
        for (int j = lane * 4; j < jend; j += 128) {
            float4 v = *(const float4*)(row + j);
            v.x = __expf(v.x - mx); v.y = __expf(v.y - mx);
            v.z = __expf(v.z - mx); v.w = __expf(v.w - mx);
            *(float4*)(row + j) = v;
            sum += v.x + v.y + v.z + v.w;
        }
        #pragma unroll
        for (int o = 16; o; o >>= 1) sum += __shfl_xor_sync(0xffffffffu, sum, o);
        const float inv = 1.0f / sum;
        if (lane == 0) sinv[w] = inv;

        if (write_attn) {
            float* arow = attn + (bh * SQ + i0 + w) * SQ;
            for (int j = lane * 4; j < jend; j += 128) {
                float4 v = *(const float4*)(row + j);
                v.x *= inv; v.y *= inv; v.z *= inv; v.w *= inv;
                *(float4*)(arow + j) = v;
            }
            const float4 z = make_float4(0.f, 0.f, 0.f, 0.f);
            for (int j = jend + lane * 4; j < SQ; j += 128)
                *(float4*)(arow + j) = z;
        }
    }

    // ======================= PV (MMA) =======================
    // warps: ks2 = w>>1 (8 key slabs of 32), ng = w&1 (d half of 32).
    const int ks2 = w >> 1;
    const int ng  = w & 1;
    float pacc[4][4] = {};

    for (int jt = 0; jt < jend; jt += KT) {
        const int ktile = min(KT, jend - jt);
        __syncthreads();
        // V^T tile: vt[d][j], stride 260, contiguous loads (pre-rounded)
        {
            const int nchunks = ktile >> 2;
            for (int idx = tid; idx < DH * nchunks; idx += 512) {
                int d = idx / nchunks, jc = (idx % nchunks) * 4;
                float4 v = *(const float4*)&gv[(bh * DH + d) * SQ + jt + jc];
                *(float4*)&kq[d * 260 + jc] = v;
            }
        }
        __syncthreads();

        const int kb2 = ks2 * 32;
        if (kb2 < ktile) {
            #pragma unroll
            for (int kk2 = 0; kk2 < 4; kk2++) {
                const int kloc = kb2 + kk2 * 8;
                uint32_t af0 = f2tf32(sc[g * SCP       + jt + kloc + tig]);
                uint32_t af1 = f2tf32(sc[(g + 8) * SCP + jt + kloc + tig]);
                uint32_t af2 = f2tf32(sc[g * SCP       + jt + kloc + tig + 4]);
                uint32_t af3 = f2tf32(sc[(g + 8) * SCP + jt + kloc + tig + 4]);
                #pragma unroll
                for (int nt = 0; nt < 4; nt++) {
                    const int d = ng * 32 + nt * 8 + g;
                    uint32_t b0 = __float_as_uint(kq[d * 260 + kloc + tig]);
                    uint32_t b1 = __float_as_uint(kq[d * 260 + kloc + tig + 4]);
                    MMA_TF32(pacc[nt], af0, af1, af2, af3, b0, b1);
                }
            }
        }
    }

    // --- reduce partials across the 8 key-slab warps ---
    __syncthreads();
    float* red = kq;   // 7 * 16 * 64 floats = 7168
    if (ks2 > 0) {
        #pragma unroll
        for (int nt = 0; nt < 4; nt++) {
            const int col = ng * 32 + nt * 8 + 2 * tig;
            *(float2*)&red[((ks2 - 1) * 16 + g) * 64 + col]     = make_float2(pacc[nt][0], pacc[nt][1]);
            *(float2*)&red[((ks2 - 1) * 16 + g + 8) * 64 + col] = make_float2(pacc[nt][2], pacc[nt][3]);
        }
    }
    __syncthreads();
    if (ks2 == 0) {
        #pragma unroll
        for (int nt = 0; nt < 4; nt++) {
            const int col = ng * 32 + nt * 8 + 2 * tig;
            #pragma unroll
            for (int half = 0; half < 2; half++) {
                const int row = g + half * 8;
                float s0 = pacc[nt][half * 2 + 0];
                float s1 = pacc[nt][half * 2 + 1];
                #pragma unroll
                for (int p = 0; p < 7; p++) {
                    s0 += red[(p * 16 + row) * 64 + col];
                    s1 += red[(p * 16 + row) * 64 + col + 1];
                }
                const float inv = sinv[row];
                *(float2*)&out[(size_t)(b * SQ + i0 + row) * EE + h * DH + col] =
                    make_float2(s0 * inv, s1 * inv);
            }
        }
    }
}

// ---------------------------------------------------------------------------
extern "C" void kernel_launch(void* const* d_in, const int* in_sizes, int n_in,
                              void* d_out, int out_size)
{
    const float* x = (const float*)d_in[0];
    const float* W = (const float*)d_in[1];
    float* out = (float*)d_out;

    const long out_elems  = (long)BB * SQ * EE;
    const long attn_elems = (long)BB * HH * SQ * SQ;
    int write_attn = ((long)out_size >= out_elems + attn_elems) ? 1 : 0;
    float* attn = write_attn ? (out + out_elems) : nullptr;

    float *gq, *gk, *gv;
    cudaGetSymbolAddress((void**)&gq, g_q);
    cudaGetSymbolAddress((void**)&gk, g_k);
    cudaGetSymbolAddress((void**)&gv, g_v);

    // QKV projection (TF32 tensor cores) + tf32-rounded scatter
    {
        int gemm_smem = 4 * ABUF * (int)sizeof(float);
        cudaFuncSetAttribute(qkv_gemm_tf32, cudaFuncAttributeMaxDynamicSharedMemorySize, gemm_smem);
        dim3 grid(GN / TN, GM / TM);
        qkv_gemm_tf32<<<grid, 256, gemm_smem>>>(x, W, gq, gk, gv);
    }

    // Fused attention (TF32 MMA, raw pre-rounded fragments)
    {
        int smem_bytes = (ROWS * SCP + 17408 + ROWS * 68 + 16) * (int)sizeof(float);
        cudaFuncSetAttribute(attn_kernel, cudaFuncAttributeMaxDynamicSharedMemorySize, smem_bytes);
        dim3 grid(SQ / ROWS, HH, BB);
        attn_kernel<<<grid, 512, smem_bytes>>>(gq, gk, gv, out, attn, write_attn);
    }
}

// round 12
// speedup vs baseline: 1.7941x; 1.1695x over previous
#include <cuda_runtime.h>
#include <math.h>
#include <stdint.h>

#define BB 4
#define SQ 2048
#define EE 1024
#define HH 16
#define DH 64
#define ROWS 16
#define KT 128

#define GM (BB*SQ)     // 8192
#define GN (3*EE)      // 3072
#define GK (EE)        // 1024

// GEMM tiling
#define TM 128
#define TN 128
#define TKS 32
#define PAD 36
#define ABUF (TM*PAD)

#define SCP 2052       // sc row pitch (mod 32 banks = 4)
#define KTP 8704       // K tile buffer stride (128*68)
#define VTP 8704       // V tile buffer stride (64*132 = 8448, padded)

// Scratch: q,k [B,H,S,Dh]; v transposed [B,H,Dh,S]  (tf32-pre-rounded)
__device__ float g_q[(size_t)BB * HH * SQ * DH];
__device__ float g_k[(size_t)BB * HH * SQ * DH];
__device__ float g_v[(size_t)BB * HH * DH * SQ];

__device__ __forceinline__ uint32_t f2tf32(float x) {
    uint32_t r;
    asm("cvt.rna.tf32.f32 %0, %1;" : "=r"(r) : "f"(x));
    return r;
}
__device__ __forceinline__ float tf32r(float x) { return __uint_as_float(f2tf32(x)); }

#define MMA_TF32(acc, a0, a1, a2, a3, b0, b1)                                \
    asm volatile(                                                            \
        "mma.sync.aligned.m16n8k8.row.col.f32.tf32.tf32.f32 "                \
        "{%0,%1,%2,%3}, {%4,%5,%6,%7}, {%8,%9}, {%0,%1,%2,%3};\n"            \
        : "+f"(acc[0]), "+f"(acc[1]), "+f"(acc[2]), "+f"(acc[3])             \
        : "r"(a0), "r"(a1), "r"(a2), "r"(a3), "r"(b0), "r"(b1))

#define CP_ASYNC16(dst, src) \
    asm volatile("cp.async.cg.shared.global [%0], [%1], 16;\n" :: "r"(dst), "l"(src))
#define CP_COMMIT()  asm volatile("cp.async.commit_group;\n" ::)
#define CP_WAIT(n)   asm volatile("cp.async.wait_group %0;\n" :: "n"(n))

// ---------------------------------------------------------------------------
// QKV GEMM (TF32): qkv = x @ W^T, scatter into g_k/g_q/g_v (tf32-rounded).
// (unchanged, validated)
// ---------------------------------------------------------------------------
__global__ __launch_bounds__(256, 2) void qkv_gemm_tf32(
    const float* __restrict__ A, const float* __restrict__ W,
    float* __restrict__ gq, float* __restrict__ gk, float* __restrict__ gv)
{
    extern __shared__ float gs[];
    float* As = gs;
    float* Bs = gs + 2 * ABUF;

    const int tid  = threadIdx.x;
    const int lane = tid & 31;
    const int wid  = tid >> 5;
    const int wm   = wid & 3;
    const int wn   = wid >> 2;
    const int g    = lane >> 2;
    const int tig  = lane & 3;
    const int m0   = blockIdx.y * TM;
    const int n0   = blockIdx.x * TN;

    const uint32_t s_base = (uint32_t)__cvta_generic_to_shared(gs);

    float acc[2][8][4] = {};

    auto issue = [&](int s, int buf) {
        const int k0 = s * TKS;
        #pragma unroll
        for (int i = 0; i < 4; i++) {
            int c   = tid + i * 256;
            int row = c >> 3;
            int kc  = (c & 7) * 4;
            const float* srcA = A + (size_t)(m0 + row) * GK + k0 + kc;
            uint32_t dstA = s_base + (uint32_t)(buf * ABUF + row * PAD + kc) * 4u;
            CP_ASYNC16(dstA, srcA);
            const float* srcB = W + (size_t)(n0 + row) * GK + k0 + kc;
            uint32_t dstB = s_base + (uint32_t)(2 * ABUF * 4u) + (uint32_t)(buf * ABUF + row * PAD + kc) * 4u;
            CP_ASYNC16(dstB, srcB);
        }
        CP_COMMIT();
    };

    const int NS = GK / TKS;
    issue(0, 0);

    for (int s = 0; s < NS; s++) {
        const int cur = s & 1;
        if (s + 1 < NS) {
            issue(s + 1, cur ^ 1);
            CP_WAIT(1);
        } else {
            CP_WAIT(0);
        }
        __syncthreads();

        const float* Ab = As + cur * ABUF + (wm * 32) * PAD;
        const float* Bb = Bs + cur * ABUF + (wn * 64) * PAD;

        #pragma unroll
        for (int kk = 0; kk < TKS; kk += 8) {
            uint32_t bf[8][2];
            #pragma unroll
            for (int nt = 0; nt < 8; nt++) {
                bf[nt][0] = f2tf32(Bb[(nt * 8 + g) * PAD + kk + tig]);
                bf[nt][1] = f2tf32(Bb[(nt * 8 + g) * PAD + kk + tig + 4]);
            }
            #pragma unroll
            for (int mt = 0; mt < 2; mt++) {
                uint32_t af[4];
                af[0] = f2tf32(Ab[(mt * 16 + g) * PAD     + kk + tig]);
                af[1] = f2tf32(Ab[(mt * 16 + g + 8) * PAD + kk + tig]);
                af[2] = f2tf32(Ab[(mt * 16 + g) * PAD     + kk + tig + 4]);
                af[3] = f2tf32(Ab[(mt * 16 + g + 8) * PAD + kk + tig + 4]);
                #pragma unroll
                for (int nt = 0; nt < 8; nt++)
                    MMA_TF32(acc[mt][nt], af[0], af[1], af[2], af[3], bf[nt][0], bf[nt][1]);
            }
        }
        __syncthreads();
    }

    #pragma unroll
    for (int mt = 0; mt < 2; mt++) {
        #pragma unroll
        for (int nt = 0; nt < 8; nt++) {
            const int cc    = n0 + wn * 64 + nt * 8 + 2 * tig;
            const int chunk = cc >> 10;
            const int hd    = (cc & 1023) >> 6;
            const int d     = cc & 63;
            #pragma unroll
            for (int half = 0; half < 2; half++) {
                const int r = m0 + wm * 32 + mt * 16 + g + half * 8;
                const int b = r >> 11, srow = r & 2047;
                const float c0 = tf32r(acc[mt][nt][half * 2 + 0]);
                const float c1 = tf32r(acc[mt][nt][half * 2 + 1]);
                const size_t bh = (size_t)(b * HH + hd);
                if (chunk == 0) {
                    *(float2*)&gk[(bh * SQ + srow) * DH + d] = make_float2(c0, c1);
                } else if (chunk == 1) {
                    *(float2*)&gq[(bh * SQ + srow) * DH + d] = make_float2(c0, c1);
                } else {
                    gv[(bh * DH + d) * SQ + srow]     = c0;
                    gv[(bh * DH + d + 1) * SQ + srow] = c1;
                }
            }
        }
    }
}

// ---------------------------------------------------------------------------
// Fused causal ALiBi attention, TF32 MMA, cp.async double-buffered tiles.
// One CTA per (b, h, 16-row query tile). 512 threads = 16 warps.
// ---------------------------------------------------------------------------
__global__ __launch_bounds__(512, 1) void attn_kernel(
    const float* __restrict__ gq, const float* __restrict__ gk,
    const float* __restrict__ gv, float* __restrict__ out,
    float* __restrict__ attn, int write_attn)
{
    extern __shared__ float smem[];
    float* sc   = smem;                    // 16 * SCP
    float* kq   = sc + ROWS * SCP;         // 2*KTP = 17408 floats
    float* qs   = kq + 2 * KTP;            // 16 * 68
    float* sinv = qs + ROWS * 68;          // 16

    const uint32_t s_kq = (uint32_t)__cvta_generic_to_shared(kq);

    const int i0 = (gridDim.x - 1 - blockIdx.x) * ROWS;   // longest tiles first
    const int h  = blockIdx.y;
    const int b  = blockIdx.z;
    const int tid  = threadIdx.x;
    const int lane = tid & 31;
    const int w    = tid >> 5;             // warp 0..15
    const int g    = lane >> 2;            // 0..7
    const int tig  = lane & 3;             // 0..3

    const size_t bh   = (size_t)(b * HH + h);
    const float slope = exp2f(-0.5f * (float)(h + 1));
    const float inv_scale = 1.0f / 32.0f;

    const int jend   = ((i0 + ROWS - 1) / 64 + 1) * 64;   // multiple of 64
    const int ntiles = (jend + KT - 1) / KT;

    // --- async fill helpers ---
    auto fill_k = [&](int t, int buf) {
        const int jt = t * KT;
        const int ktile = min(KT, jend - jt);
        for (int idx = tid; idx < ktile * 16; idx += 512) {
            int key = idx >> 4, dc = (idx & 15) * 4;
            CP_ASYNC16(s_kq + (uint32_t)(buf * KTP + key * 68 + dc) * 4u,
                       &gk[(bh * SQ + jt + key) * DH + dc]);
        }
        CP_COMMIT();
    };
    auto fill_v = [&](int t, int buf) {
        const int jt = t * KT;
        const int ktile = min(KT, jend - jt);
        if (ktile == KT) {
            for (int idx = tid; idx < 64 * 32; idx += 512) {
                int d = idx >> 5, jc = (idx & 31) * 4;
                CP_ASYNC16(s_kq + (uint32_t)(buf * VTP + d * 132 + jc) * 4u,
                           &gv[(bh * DH + d) * SQ + jt + jc]);
            }
        } else {   // 64-key tail
            for (int idx = tid; idx < 64 * 16; idx += 512) {
                int d = idx >> 4, jc = (idx & 15) * 4;
                CP_ASYNC16(s_kq + (uint32_t)(buf * VTP + d * 132 + jc) * 4u,
                           &gv[(bh * DH + d) * SQ + jt + jc]);
            }
        }
        CP_COMMIT();
    };

    // kick off first K tile immediately (overlaps with Q load)
    fill_k(0, 0);

    // --- load Q (16 x 64), pre-rounded tf32 ---
    if (tid < 256) {
        int r = tid >> 4, dc = (tid & 15) * 4;
        float4 v = *(const float4*)&gq[(bh * SQ + i0 + r) * DH + dc];
        *(float4*)&qs[r * 68 + dc] = v;
    }
    __syncthreads();

    // --- preload Q fragments (rows g, g+8), raw bits ---
    uint32_t qa[8][4];
    #pragma unroll
    for (int kk = 0; kk < 8; kk++) {
        qa[kk][0] = __float_as_uint(qs[g * 68       + kk * 8 + tig]);
        qa[kk][1] = __float_as_uint(qs[(g + 8) * 68 + kk * 8 + tig]);
        qa[kk][2] = __float_as_uint(qs[g * 68       + kk * 8 + tig + 4]);
        qa[kk][3] = __float_as_uint(qs[(g + 8) * 68 + kk * 8 + tig + 4]);
    }

    // ======================= scores (MMA, double-buffered) =======================
    for (int t = 0; t < ntiles; t++) {
        const int cur = t & 1;
        const int jt  = t * KT;
        const int ktile = min(KT, jend - jt);
        if (t + 1 < ntiles) { fill_k(t + 1, cur ^ 1); CP_WAIT(1); }
        else                { CP_WAIT(0); }
        __syncthreads();

        if (w * 8 < ktile) {
            const float* ktb = kq + cur * KTP + (w * 8 + g) * 68;
            float acc[4] = {};
            #pragma unroll
            for (int kk = 0; kk < 8; kk++) {
                uint32_t b0 = __float_as_uint(ktb[kk * 8 + tig]);
                uint32_t b1 = __float_as_uint(ktb[kk * 8 + tig + 4]);
                MMA_TF32(acc, qa[kk][0], qa[kk][1], qa[kk][2], qa[kk][3], b0, b1);
            }
            const int j0 = jt + w * 8 + 2 * tig;
            #pragma unroll
            for (int half = 0; half < 2; half++) {
                const int row = g + half * 8;
                const int gi  = i0 + row;
                float v0 = (j0     <= gi) ? fmaf(slope, (float)(j0 - gi),     acc[half*2+0] * inv_scale) : -INFINITY;
                float v1 = (j0 + 1 <= gi) ? fmaf(slope, (float)(j0 + 1 - gi), acc[half*2+1] * inv_scale) : -INFINITY;
                *(float2*)&sc[row * SCP + j0] = make_float2(v0, v1);
            }
        }
        __syncthreads();
    }

    // prefetch first V tile; it lands while softmax runs
    fill_v(0, 0);

    // ======================= softmax (warp w owns row w) =======================
    {
        float* row = sc + w * SCP;
        float mx = -INFINITY;
        for (int j = lane * 4; j < jend; j += 128) {
            float4 v = *(const float4*)(row + j);
            mx = fmaxf(mx, fmaxf(fmaxf(v.x, v.y), fmaxf(v.z, v.w)));
        }
        #pragma unroll
        for (int o = 16; o; o >>= 1) mx = fmaxf(mx, __shfl_xor_sync(0xffffffffu, mx, o));
        float sum = 0.f;
        for (int j = lane * 4; j < jend; j += 128) {
            float4 v = *(const float4*)(row + j);
            v.x = __expf(v.x - mx); v.y = __expf(v.y - mx);
            v.z = __expf(v.z - mx); v.w = __expf(v.w - mx);
            *(float4*)(row + j) = v;
            sum += v.x + v.y + v.z + v.w;
        }
        #pragma unroll
        for (int o = 16; o; o >>= 1) sum += __shfl_xor_sync(0xffffffffu, sum, o);
        const float inv = 1.0f / sum;
        if (lane == 0) sinv[w] = inv;

        if (write_attn) {
            float* arow = attn + (bh * SQ + i0 + w) * SQ;
            for (int j = lane * 4; j < jend; j += 128) {
                float4 v = *(const float4*)(row + j);
                v.x *= inv; v.y *= inv; v.z *= inv; v.w *= inv;
                *(float4*)(arow + j) = v;
            }
            const float4 z = make_float4(0.f, 0.f, 0.f, 0.f);
            for (int j = jend + lane * 4; j < SQ; j += 128)
                *(float4*)(arow + j) = z;
        }
    }

    // ======================= PV (MMA, double-buffered) =======================
    // warps: ks2 = w>>1 (8 key slabs of 16), ng = w&1 (d half of 32).
    const int ks2 = w >> 1;
    const int ng  = w & 1;
    float pacc[4][4] = {};

    for (int t = 0; t < ntiles; t++) {
        const int cur = t & 1;
        const int jt  = t * KT;
        const int ktile = min(KT, jend - jt);
        if (t + 1 < ntiles) { fill_v(t + 1, cur ^ 1); CP_WAIT(1); }
        else                { CP_WAIT(0); }
        __syncthreads();

        const int kb2 = ks2 * 16;
        if (kb2 < ktile) {
            const float* vtb = kq + cur * VTP;
            #pragma unroll
            for (int kk2 = 0; kk2 < 2; kk2++) {
                const int kloc = kb2 + kk2 * 8;
                uint32_t af0 = f2tf32(sc[g * SCP       + jt + kloc + tig]);
                uint32_t af1 = f2tf32(sc[(g + 8) * SCP + jt + kloc + tig]);
                uint32_t af2 = f2tf32(sc[g * SCP       + jt + kloc + tig + 4]);
                uint32_t af3 = f2tf32(sc[(g + 8) * SCP + jt + kloc + tig + 4]);
                #pragma unroll
                for (int nt = 0; nt < 4; nt++) {
                    const int d = ng * 32 + nt * 8 + g;
                    uint32_t b0 = __float_as_uint(vtb[d * 132 + kloc + tig]);
                    uint32_t b1 = __float_as_uint(vtb[d * 132 + kloc + tig + 4]);
                    MMA_TF32(pacc[nt], af0, af1, af2, af3, b0, b1);
                }
            }
        }
        __syncthreads();
    }

    // --- reduce partials across the 8 key-slab warps (overlay on kq) ---
    float* red = kq;   // 7 * 16 * 64 floats = 7168
    if (ks2 > 0) {
        #pragma unroll
        for (int nt = 0; nt < 4; nt++) {
            const int col = ng * 32 + nt * 8 + 2 * tig;
            *(float2*)&red[((ks2 - 1) * 16 + g) * 64 + col]     = make_float2(pacc[nt][0], pacc[nt][1]);
            *(float2*)&red[((ks2 - 1) * 16 + g + 8) * 64 + col] = make_float2(pacc[nt][2], pacc[nt][3]);
        }
    }
    __syncthreads();
    if (ks2 == 0) {
        #pragma unroll
        for (int nt = 0; nt < 4; nt++) {
            const int col = ng * 32 + nt * 8 + 2 * tig;
            #pragma unroll
            for (int half = 0; half < 2; half++) {
                const int row = g + half * 8;
                float s0 = pacc[nt][half * 2 + 0];
                float s1 = pacc[nt][half * 2 + 1];
                #pragma unroll
                for (int p = 0; p < 7; p++) {
                    s0 += red[(p * 16 + row) * 64 + col];
                    s1 += red[(p * 16 + row) * 64 + col + 1];
                }
                const float inv = sinv[row];
                *(float2*)&out[(size_t)(b * SQ + i0 + row) * EE + h * DH + col] =
                    make_float2(s0 * inv, s1 * inv);
            }
        }
    }
}

// ---------------------------------------------------------------------------
extern "C" void kernel_launch(void* const* d_in, const int* in_sizes, int n_in,
                              void* d_out, int out_size)
{
    const float* x = (const float*)d_in[0];
    const float* W = (const float*)d_in[1];
    float* out = (float*)d_out;

    const long out_elems  = (long)BB * SQ * EE;
    const long attn_elems = (long)BB * HH * SQ * SQ;
    int write_attn = ((long)out_size >= out_elems + attn_elems) ? 1 : 0;
    float* attn = write_attn ? (out + out_elems) : nullptr;

    float *gq, *gk, *gv;
    cudaGetSymbolAddress((void**)&gq, g_q);
    cudaGetSymbolAddress((void**)&gk, g_k);
    cudaGetSymbolAddress((void**)&gv, g_v);

    // QKV projection (TF32 tensor cores) + tf32-rounded scatter
    {
        int gemm_smem = 4 * ABUF * (int)sizeof(float);
        cudaFuncSetAttribute(qkv_gemm_tf32, cudaFuncAttributeMaxDynamicSharedMemorySize, gemm_smem);
        dim3 grid(GN / TN, GM / TM);
        qkv_gemm_tf32<<<grid, 256, gemm_smem>>>(x, W, gq, gk, gv);
    }

    // Fused attention (TF32 MMA, cp.async double-buffered)
    {
        int smem_bytes = (ROWS * SCP + 2 * KTP + ROWS * 68 + 16) * (int)sizeof(float);
        cudaFuncSetAttribute(attn_kernel, cudaFuncAttributeMaxDynamicSharedMemorySize, smem_bytes);
        dim3 grid(SQ / ROWS, HH, BB);
        attn_kernel<<<grid, 512, smem_bytes>>>(gq, gk, gv, out, attn, write_attn);
    }
}